// round 14
// baseline (speedup 1.0000x reference)
#include <cuda_runtime.h>
#include <cuda_bf16.h>

// LoRA: out[b,s,o] = scaling * sum_r ( sum_i x[b,s,i] * A[r,i] ) * B[o,r]
// x: [4, 8192, 1024] f32   A: [4, 1024] f32   B: [1024, 4] f32   scaling = 0.25
//
// History: R4 MLP1 (232us) -> R5 occ11% (69us) -> R6 24-warp/MLP8 but L1 83%
// (49.9us) -> R7 2-row LDS share (47.5us) -> R8 packed neutral -> R9 SW
// pipeline regressed -> R11 4-row share: L1 63->43% but DRAM flat at 63%,
// concurrency-bound at 16 warps/SM (47.2us). R12/R13 (resubmit after infra
// failure): keep 4-row LDS sharing, shrink x burst to xv[4][2] (8 LDG.128)
// and cap regs at 84 -> 3 CTAs -> 24 warps/SM. More warps x slightly smaller
// bursts = higher time-averaged bytes in flight; L1 headroom from R11
// absorbs the extra issue traffic.

#define LORA_NROWS   (4 * 8192)   // 32768 token rows
#define LORA_NF4     256          // 1024 floats / 4 -> float4 chunks per row
#define LORA_BLOCK   256
#define LORA_WARPS   8
#define LORA_GRID    1024         // 8192 warps == 8192 quads, exactly 1 each
#define LORA_SCALE   0.25f

__device__ __forceinline__ float4 ldcs4(const float4* p) {
    float4 v;
    asm("ld.global.cs.v4.f32 {%0, %1, %2, %3}, [%4];"
        : "=f"(v.x), "=f"(v.y), "=f"(v.z), "=f"(v.w) : "l"(p));
    return v;
}
__device__ __forceinline__ void stcs4(float4* p, float4 v) {
    asm("st.global.cs.v4.f32 [%0], {%1, %2, %3, %4};"
        :: "l"(p), "f"(v.x), "f"(v.y), "f"(v.z), "f"(v.w) : "memory");
}

__global__ __launch_bounds__(LORA_BLOCK, 3)
void lora_fused_kernel(const float* __restrict__ x,
                       const float* __restrict__ A,
                       const float* __restrict__ B,
                       float* __restrict__ out)
{
    __shared__ float sA[4 * 1024];   // rank-major, same as global A layout
    __shared__ float sBt[4 * 1024];  // TRANSPOSED: sBt[r*1024 + o] = B[o*4 + r]

    const int tid = threadIdx.x;

    // ---- Stage A (direct float4 copy) and B (transpose) into smem ----
    {
        const float4* A4  = reinterpret_cast<const float4*>(A);
        float4*       sA4 = reinterpret_cast<float4*>(sA);
        #pragma unroll
        for (int i = 0; i < 4; i++)
            sA4[tid + i * 256] = A4[tid + i * 256];

        const float4* B4 = reinterpret_cast<const float4*>(B);  // one float4 = one B row
        #pragma unroll
        for (int i = 0; i < 4; i++) {
            int o = tid + i * 256;
            float4 b = B4[o];
            sBt[0 * 1024 + o] = b.x;
            sBt[1 * 1024 + o] = b.y;
            sBt[2 * 1024 + o] = b.z;
            sBt[3 * 1024 + o] = b.w;
        }
    }
    __syncthreads();

    const int lane = tid & 31;
    const int wid  = tid >> 5;
    const int warp_global = blockIdx.x * LORA_WARPS + wid;

    const float4* sA4c = reinterpret_cast<const float4*>(sA);
    const float4* sB0  = reinterpret_cast<const float4*>(sBt);
    const float4* sB1  = reinterpret_cast<const float4*>(sBt + 1024);
    const float4* sB2  = reinterpret_cast<const float4*>(sBt + 2048);
    const float4* sB3  = reinterpret_cast<const float4*>(sBt + 3072);

    // Each warp owns exactly 4 consecutive rows (8192 warps x 4 = 32768).
    const size_t row0 = (size_t)warp_global * 4;
    const float4* xr = reinterpret_cast<const float4*>(x) + row0 * LORA_NF4;

    float acc[4][4];   // [row][rank]
    #pragma unroll
    for (int r = 0; r < 4; r++)
        #pragma unroll
        for (int k = 0; k < 4; k++) acc[r][k] = 0.f;

    // ---- Pass 1 in four quarter-bursts; each: 8 LDG.128 (MLP=8),
    //      A tile chunk shared by all 4 rows. Small live set -> 84-reg fit.
    #pragma unroll
    for (int h = 0; h < 4; h++) {
        float4 xv[4][2];   // [row][chunk-within-quarter]
        #pragma unroll
        for (int r = 0; r < 4; r++)
            #pragma unroll
            for (int j = 0; j < 2; j++)
                xv[r][j] = ldcs4(&xr[r * LORA_NF4 + (h * 2 + j) * 32 + lane]);

        #pragma unroll
        for (int j = 0; j < 2; j++) {
            int idx = (h * 2 + j) * 32 + lane;
            float4 a0 = sA4c[0 * 256 + idx];
            float4 a1 = sA4c[1 * 256 + idx];
            float4 a2 = sA4c[2 * 256 + idx];
            float4 a3 = sA4c[3 * 256 + idx];
            #pragma unroll
            for (int r = 0; r < 4; r++) {
                float4 v = xv[r][j];
                acc[r][0] = fmaf(v.x, a0.x, fmaf(v.y, a0.y, fmaf(v.z, a0.z, fmaf(v.w, a0.w, acc[r][0]))));
                acc[r][1] = fmaf(v.x, a1.x, fmaf(v.y, a1.y, fmaf(v.z, a1.z, fmaf(v.w, a1.w, acc[r][1]))));
                acc[r][2] = fmaf(v.x, a2.x, fmaf(v.y, a2.y, fmaf(v.z, a2.z, fmaf(v.w, a2.w, acc[r][2]))));
                acc[r][3] = fmaf(v.x, a3.x, fmaf(v.y, a3.y, fmaf(v.z, a3.z, fmaf(v.w, a3.w, acc[r][3]))));
            }
        }
    }

    // ---- Warp butterfly reduce all 16 sums; every lane gets full values ----
    #pragma unroll
    for (int off = 16; off > 0; off >>= 1) {
        #pragma unroll
        for (int r = 0; r < 4; r++) {
            acc[r][0] += __shfl_xor_sync(0xffffffffu, acc[r][0], off);
            acc[r][1] += __shfl_xor_sync(0xffffffffu, acc[r][1], off);
            acc[r][2] += __shfl_xor_sync(0xffffffffu, acc[r][2], off);
            acc[r][3] += __shfl_xor_sync(0xffffffffu, acc[r][3], off);
        }
    }
    #pragma unroll
    for (int r = 0; r < 4; r++)
        #pragma unroll
        for (int k = 0; k < 4; k++) acc[r][k] *= LORA_SCALE;

    // ---- Pass 2: B tile chunk shared by all 4 rows ----
    float4* orow = reinterpret_cast<float4*>(out) + row0 * LORA_NF4;
    #pragma unroll
    for (int j = 0; j < 8; j++) {
        int idx = j * 32 + lane;
        float4 b0 = sB0[idx];
        float4 b1 = sB1[idx];
        float4 b2 = sB2[idx];
        float4 b3 = sB3[idx];
        #pragma unroll
        for (int r = 0; r < 4; r++) {
            float4 o;
            o.x = fmaf(acc[r][0], b0.x, fmaf(acc[r][1], b1.x, fmaf(acc[r][2], b2.x, acc[r][3] * b3.x)));
            o.y = fmaf(acc[r][0], b0.y, fmaf(acc[r][1], b1.y, fmaf(acc[r][2], b2.y, acc[r][3] * b3.y)));
            o.z = fmaf(acc[r][0], b0.z, fmaf(acc[r][1], b1.z, fmaf(acc[r][2], b2.z, acc[r][3] * b3.z)));
            o.w = fmaf(acc[r][0], b0.w, fmaf(acc[r][1], b1.w, fmaf(acc[r][2], b2.w, acc[r][3] * b3.w)));
            stcs4(&orow[r * LORA_NF4 + idx], o);
        }
    }
}

extern "C" void kernel_launch(void* const* d_in, const int* in_sizes, int n_in,
                              void* d_out, int out_size)
{
    const float* x = (const float*)d_in[0];   // [4, 8192, 1024]
    const float* A = (const float*)d_in[1];   // [4, 1024]
    const float* B = (const float*)d_in[2];   // [1024, 4]
    float* out     = (float*)d_out;           // [4, 8192, 1024]

    lora_fused_kernel<<<LORA_GRID, LORA_BLOCK>>>(x, A, B, out);
}